// round 2
// baseline (speedup 1.0000x reference)
#include <cuda_runtime.h>

// DilatedReparamBlock collapsed into a single 13x13 depthwise conv + bias.
//
// Stage 1 (prep_kernel): fold 7 branches (large-kernel + 6 dilated) and their
//   BN affines into one equivalent per-channel 13x13 weight + bias.
// Stage 2 (conv_kernel): depthwise 13x13 conv, fp32. One block per (b,c)
//   image; input tile (+6 halo, zero-padded) in shared memory; each thread
//   computes an 8-wide x 2-row output patch with a 20-float register window.

#define CC 256
#define HW 56
#define PAD 6
#define SROWS 68          // 56 + 2*6
#define SSTR  72          // row stride in floats (16B-aligned rows for float4)
#define NTHR 224          // 7 warps: 7 col-groups x 32 row-pairs

__device__ float g_weq[CC * 169];
__device__ float g_bias[CC];

__global__ void prep_kernel(const float* __restrict__ lk_w,
                            const float* __restrict__ w0, const float* __restrict__ w1,
                            const float* __restrict__ w2, const float* __restrict__ w3,
                            const float* __restrict__ w4, const float* __restrict__ w5,
                            const float* __restrict__ gamma, const float* __restrict__ beta,
                            const float* __restrict__ mean,  const float* __restrict__ var)
{
    int c = blockIdx.x;
    int t = threadIdx.x;

    float s[7], sh[7];
#pragma unroll
    for (int i = 0; i < 7; i++) {
        float sc = gamma[i * CC + c] * rsqrtf(var[i * CC + c] + 1e-5f);
        s[i]  = sc;
        sh[i] = beta[i * CC + c] - mean[i * CC + c] * sc;
    }
    if (t == 0)
        g_bias[c] = sh[0] + sh[1] + sh[2] + sh[3] + sh[4] + sh[5] + sh[6];

    if (t < 169) {
        int ty = t / 13, tx = t % 13;
        int dy = ty - PAD, dx = tx - PAD;
        float acc = s[0] * lk_w[c * 169 + t];

        const float* ws[6]  = { w0, w1, w2, w3, w4, w5 };
        const int    KSa[6]  = { 5, 7, 7, 3, 3, 3 };
        const int    DILa[6] = { 1, 1, 2, 3, 4, 5 };
#pragma unroll
        for (int j = 0; j < 6; j++) {
            int r = DILa[j], k = KSa[j];
            if (dy % r == 0 && dx % r == 0) {
                int a  = dy / r + (k - 1) / 2;
                int b2 = dx / r + (k - 1) / 2;
                if (a >= 0 && a < k && b2 >= 0 && b2 < k)
                    acc += s[j + 1] * ws[j][c * k * k + a * k + b2];
            }
        }
        g_weq[c * 169 + t] = acc;
    }
}

__global__ void __launch_bounds__(NTHR) conv_kernel(const float* __restrict__ x,
                                                    float* __restrict__ out)
{
    __shared__ float sx[SROWS * SSTR];
    __shared__ float sw[169];
    __shared__ float sbias;

    int bc = blockIdx.x;                       // b*256 + c
    const float* xim = x   + (size_t)bc * (HW * HW);
    float*       oim = out + (size_t)bc * (HW * HW);
    int tid = threadIdx.x;

    // Fill 68x68 padded tile (zero halo). Coalesced global reads.
    for (int idx = tid; idx < SROWS * SROWS; idx += NTHR) {
        int r  = idx / SROWS;
        int cc2 = idx - r * SROWS;
        int iy = r - PAD, ix = cc2 - PAD;
        float v = 0.f;
        if ((unsigned)iy < (unsigned)HW && (unsigned)ix < (unsigned)HW)
            v = xim[iy * HW + ix];
        sx[r * SSTR + cc2] = v;
    }
    int c = bc & (CC - 1);
    for (int t = tid; t < 169; t += NTHR) sw[t] = g_weq[c * 169 + t];
    if (tid == 0) sbias = g_bias[c];
    __syncthreads();

    // Thread -> 8-wide x 2-row output patch.
    int colb = tid % 7;                        // 0..6  -> ox0 = colb*8
    int pair = tid / 7;                        // 0..31 -> oy0 = pair*2
    int oy0  = pair * 2;
    if (oy0 >= HW) return;                     // 28 idle threads
    int ox0 = colb * 8;

    float acc0[8], acc1[8];
#pragma unroll
    for (int o = 0; o < 8; o++) { acc0[o] = 0.f; acc1[o] = 0.f; }

    // Walk 14 input rows; row iy feeds output row 0 (ky=iy) and row 1 (ky=iy-1).
#pragma unroll 1
    for (int iy = 0; iy < 14; iy++) {
        float xw[20];
        const float4* xr =
            reinterpret_cast<const float4*>(&sx[(oy0 + iy) * SSTR + ox0]);
#pragma unroll
        for (int q = 0; q < 5; q++) {
            float4 v4 = xr[q];
            xw[q * 4 + 0] = v4.x; xw[q * 4 + 1] = v4.y;
            xw[q * 4 + 2] = v4.z; xw[q * 4 + 3] = v4.w;
        }
        if (iy < 13) {
            const float* wr = &sw[iy * 13];
#pragma unroll
            for (int kx = 0; kx < 13; kx++) {
                float w = wr[kx];
#pragma unroll
                for (int o = 0; o < 8; o++)
                    acc0[o] = fmaf(xw[kx + o], w, acc0[o]);
            }
        }
        if (iy >= 1) {
            const float* wr = &sw[(iy - 1) * 13];
#pragma unroll
            for (int kx = 0; kx < 13; kx++) {
                float w = wr[kx];
#pragma unroll
                for (int o = 0; o < 8; o++)
                    acc1[o] = fmaf(xw[kx + o], w, acc1[o]);
            }
        }
    }

    float bb = sbias;
    float4* o0 = reinterpret_cast<float4*>(&oim[oy0 * HW + ox0]);
    float4* o1 = reinterpret_cast<float4*>(&oim[(oy0 + 1) * HW + ox0]);
    o0[0] = make_float4(acc0[0] + bb, acc0[1] + bb, acc0[2] + bb, acc0[3] + bb);
    o0[1] = make_float4(acc0[4] + bb, acc0[5] + bb, acc0[6] + bb, acc0[7] + bb);
    o1[0] = make_float4(acc1[0] + bb, acc1[1] + bb, acc1[2] + bb, acc1[3] + bb);
    o1[1] = make_float4(acc1[4] + bb, acc1[5] + bb, acc1[6] + bb, acc1[7] + bb);
}

extern "C" void kernel_launch(void* const* d_in, const int* in_sizes, int n_in,
                              void* d_out, int out_size)
{
    const float* x    = (const float*)d_in[0];
    const float* lk_w = (const float*)d_in[1];
    const float* w0   = (const float*)d_in[2];
    const float* w1   = (const float*)d_in[3];
    const float* w2   = (const float*)d_in[4];
    const float* w3   = (const float*)d_in[5];
    const float* w4   = (const float*)d_in[6];
    const float* w5   = (const float*)d_in[7];
    const float* g    = (const float*)d_in[8];
    const float* b    = (const float*)d_in[9];
    const float* m    = (const float*)d_in[10];
    const float* v    = (const float*)d_in[11];
    float* out = (float*)d_out;

    prep_kernel<<<CC, 192>>>(lk_w, w0, w1, w2, w3, w4, w5, g, b, m, v);

    int nimg = out_size / (HW * HW);           // 32 * 256 = 8192
    conv_kernel<<<nimg, NTHR>>>(x, out);
}